// round 14
// baseline (speedup 1.0000x reference)
#include <cuda_runtime.h>
#include <math.h>

// Rotated-IoU loss, one thread per pair. Reference decision structure
// (validated rel_err ~4.966e-4 across R11/R12/R13). R14:
//  - gather: candidates computed unconditionally, stores PREDICATED
//    (single-statement if -> @P STL, no BSSY/BSYNC divergence envelopes;
//    R12 failed because its stores were unconditional, not because of
//    branchlessness)
//  - cheaper monotone pseudo-angle: copysign(1 - x/(|x|+|y|), y)
//  - __launch_bounds__(128, 9): 9 CTAs/SM at 56 regs
//  - fast path (warp-uniform k<=8): 8-key Batcher network, as R13
//  - slow path (rare): R11 rank loop, as R13

__device__ __forceinline__ float pseudo_angle(float x, float y)
{
    float d = fabsf(x) + fabsf(y);
    float r = (d > 0.f) ? __fdividef(x, d) : 1.f;   // d==0 -> p = +/-0
    return copysignf(1.f - r, y);                    // monotone w.r.t. atan2
}

__device__ __forceinline__ unsigned int order_key(float a)
{
    unsigned int u = __float_as_uint(a);
    return (u & 0x80000000u) ? ~u : (u | 0x80000000u);
}

__global__ void __launch_bounds__(128, 9)
riou_kernel(const float* __restrict__ pred,
            const float* __restrict__ tgt,
            float* __restrict__ out, int n)
{
    int i = blockIdx.x * blockDim.x + threadIdx.x;
    if (i >= n) return;

    const float2* pp = reinterpret_cast<const float2*>(pred) + (size_t)i * 3;
    const float2* tp = reinterpret_cast<const float2*>(tgt)  + (size_t)i * 3;
    float2 a0 = pp[0], a1 = pp[1], a2 = pp[2];
    float2 b0 = tp[0], b1 = tp[1], b2 = tp[2];

    const float x1c = a0.x, y1c = a0.y, w1 = a1.x, h1 = a1.y;
    const float x2c = b0.x, y2c = b0.y, w2 = b1.x, h2 = b1.y;

    float inv1 = rsqrtf(a2.x * a2.x + a2.y * a2.y);
    float s1 = a2.x * inv1, c1 = a2.y * inv1;
    float inv2 = rsqrtf(b2.x * b2.x + b2.y * b2.y);
    float s2 = b2.x * inv2, c2 = b2.y * inv2;

    const float dxv[4] = {0.5f, -0.5f, -0.5f, 0.5f};
    const float dyv[4] = {0.5f, 0.5f, -0.5f, -0.5f};
    float c1x[4], c1y[4], c2x[4], c2y[4];
#pragma unroll
    for (int j = 0; j < 4; j++) {
        float cx = dxv[j] * w1, cy = dyv[j] * h1;
        c1x[j] = cx * c1 - cy * s1 + x1c;
        c1y[j] = cx * s1 + cy * c1 + y1c;
    }
#pragma unroll
    for (int j = 0; j < 4; j++) {
        float cx = dxv[j] * w2, cy = dyv[j] * h2;
        c2x[j] = cx * c2 - cy * s2 + x2c;
        c2y[j] = cx * s2 + cy * c2 + y2c;
    }

    // ---- gather valid candidate vertices (predicated stores) ----
    float2 v[16];
    int    k = 0;
    float  sumx = 0.f, sumy = 0.f;
    const float eps = 1e-6f;

    // corners of box1 inside box2
    {
        float ax = c2x[0], ay = c2y[0];
        float abx = c2x[1] - ax, aby = c2y[1] - ay;
        float adx = c2x[3] - ax, ady = c2y[3] - ay;
        float den_ab = abx * abx + aby * aby;
        float den_ad = adx * adx + ady * ady;
        float base_ab = abx * ax + aby * ay;
        float base_ad = adx * ax + ady * ay;
        float lo_ab = -eps * den_ab, hi_ab = (1.f + eps) * den_ab;
        float lo_ad = -eps * den_ad, hi_ad = (1.f + eps) * den_ad;
#pragma unroll
        for (int j = 0; j < 4; j++) {
            float d_ab = abx * c1x[j] + aby * c1y[j] - base_ab;
            float d_ad = adx * c1x[j] + ady * c1y[j] - base_ad;
            bool ok = (d_ab > lo_ab) & (d_ab < hi_ab) & (d_ad > lo_ad) & (d_ad < hi_ad);
            if (ok) v[k] = make_float2(c1x[j], c1y[j]);
            sumx += ok ? c1x[j] : 0.f;
            sumy += ok ? c1y[j] : 0.f;
            k += (int)ok;
        }
    }
    // corners of box2 inside box1
    {
        float ax = c1x[0], ay = c1y[0];
        float abx = c1x[1] - ax, aby = c1y[1] - ay;
        float adx = c1x[3] - ax, ady = c1y[3] - ay;
        float den_ab = abx * abx + aby * aby;
        float den_ad = adx * adx + ady * ady;
        float base_ab = abx * ax + aby * ay;
        float base_ad = adx * ax + ady * ay;
        float lo_ab = -eps * den_ab, hi_ab = (1.f + eps) * den_ab;
        float lo_ad = -eps * den_ad, hi_ad = (1.f + eps) * den_ad;
#pragma unroll
        for (int j = 0; j < 4; j++) {
            float d_ab = abx * c2x[j] + aby * c2y[j] - base_ab;
            float d_ad = adx * c2x[j] + ady * c2y[j] - base_ad;
            bool ok = (d_ab > lo_ab) & (d_ab < hi_ab) & (d_ad > lo_ad) & (d_ad < hi_ad);
            if (ok) v[k] = make_float2(c2x[j], c2y[j]);
            sumx += ok ? c2x[j] : 0.f;
            sumy += ok ? c2y[j] : 0.f;
            k += (int)ok;
        }
    }
    // 4x4 edge intersections, invariants hoisted, predicated stores
    float gxv[4], gyv[4], hq[4];
#pragma unroll
    for (int e2 = 0; e2 < 4; e2++) {
        int e2n = (e2 + 1) & 3;
        float gx = c2x[e2n] - c2x[e2];
        float gy = c2y[e2n] - c2y[e2];
        gxv[e2] = gx; gyv[e2] = gy;
        hq[e2] = gx * c2y[e2] - gy * c2x[e2];
    }
#pragma unroll
    for (int e1 = 0; e1 < 4; e1++) {
        float X1 = c1x[e1], Y1 = c1y[e1];
        float ex = c1x[(e1 + 1) & 3] - X1, ey = c1y[(e1 + 1) & 3] - Y1;
        float hp = ex * Y1 - ey * X1;
#pragma unroll
        for (int e2 = 0; e2 < 4; e2++) {
            float gx = gxv[e2], gy = gyv[e2];
            float num_t = ex * c2y[e2] - ey * c2x[e2] - hp;
            float den   = ey * gx - ex * gy;
            float num_u = gx * Y1 - gy * X1 - hq[e2];
            float ad = fabsf(den);
            bool ok = (num_t * den > 0.f) & (fabsf(num_t) < ad)
                    & (num_u * den < 0.f) & (fabsf(num_u) < ad);
            float t = __fdividef(num_t, den);
            float ix = X1 + t * ex, iy = Y1 + t * ey;
            if (ok) v[k] = make_float2(ix, iy);
            sumx += ok ? ix : 0.f;
            sumy += ok ? iy : 0.f;
            k += (int)ok;
        }
    }

    // ---- center ----
    float invk = __fdividef(1.f, (float)(k > 0 ? k : 1));
    float meanx = sumx * invk, meany = sumy * invk;

    float cr = 0.f;
    unsigned int mask = __activemask();
    bool small = __all_sync(mask, k <= 8);

    if (small) {
        // ===== FAST PATH: 8 register keys, Batcher n=8 network =====
        unsigned int key[8];
#pragma unroll
        for (int j = 0; j < 8; j++) {
            float2 c = v[j];
            float vx = c.x - meanx, vy = c.y - meany;
            unsigned int kj = (order_key(pseudo_angle(vx, vy)) & ~15u) | (unsigned)j;
            key[j] = (j < k) ? kj : (0xFFFFFFF0u | (unsigned)j);
        }
#define CE(a, b) { unsigned int lo = min(key[a], key[b]); \
                   unsigned int hi = max(key[a], key[b]); \
                   key[a] = lo; key[b] = hi; }
        CE(0,1) CE(2,3) CE(4,5) CE(6,7)
        CE(0,2) CE(1,3) CE(4,6) CE(5,7)
        CE(1,2) CE(5,6)
        CE(0,4) CE(1,5) CE(2,6) CE(3,7)
        CE(2,4) CE(3,5)
        CE(1,2) CE(3,4) CE(5,6)
#undef CE
        int idx0 = (int)(key[0] & 15u);
        float2 f = v[idx0];
        float fx = f.x - meanx, fy = f.y - meany;
        float prx = fx, pry = fy;
#pragma unroll
        for (int j = 1; j < 8; j++) {
            int idx = (int)(key[j] & 15u);
            idx = (j < k) ? idx : idx0;       // pad duplicates slot 0
            float2 c = v[idx];
            float cx = c.x - meanx, cy = c.y - meany;
            cr += prx * cy - pry * cx;        // at j==k this IS the wrap term
            prx = cx; pry = cy;
        }
        cr += prx * fy - pry * fx;            // zero when k<8
        cr = (k > 0) ? cr : 0.f;
    } else {
        // ===== SLOW PATH (rare): rank loop + packed-perm walk =====
        unsigned int ku[16];
#pragma unroll 4
        for (int j = 0; j < k; j++) {
            float vx = v[j].x - meanx, vy = v[j].y - meany;
            ku[j] = (order_key(pseudo_angle(vx, vy)) & ~15u) | (unsigned)j;
        }
        unsigned long long perm = 0ull;
        for (int ii = 0; ii < k; ii++) {
            unsigned int ki = ku[ii];
            int r = 0;
#pragma unroll 4
            for (int jj = 0; jj < k; jj++)
                r += (int)(ku[jj] < ki);
            perm |= (unsigned long long)(unsigned)ii << (4 * r);
        }
        if (k > 0) {
            int idx0 = (int)(perm & 15ull);
            float2 f = v[idx0];
            float fx = f.x - meanx, fy = f.y - meany;
            float prx = fx, pry = fy;
            unsigned long long pw = perm >> 4;
#pragma unroll 4
            for (int j = 1; j < k; j++) {
                int idx = (int)(pw & 15ull);
                pw >>= 4;
                float2 c = v[idx];
                float cx = c.x - meanx, cy = c.y - meany;
                cr += prx * cy - pry * cx;
                prx = cx; pry = cy;
            }
            cr += prx * fy - pry * fx;
        }
    }
    float inter = 0.5f * fabsf(cr);

    // ---- enclosing box + loss ----
    float xmin = c1x[0], xmax = c1x[0], ymin = c1y[0], ymax = c1y[0];
#pragma unroll
    for (int j = 1; j < 4; j++) {
        xmin = fminf(xmin, c1x[j]); xmax = fmaxf(xmax, c1x[j]);
        ymin = fminf(ymin, c1y[j]); ymax = fmaxf(ymax, c1y[j]);
    }
#pragma unroll
    for (int j = 0; j < 4; j++) {
        xmin = fminf(xmin, c2x[j]); xmax = fmaxf(xmax, c2x[j]);
        ymin = fminf(ymin, c2y[j]); ymax = fmaxf(ymax, c2y[j]);
    }
    float wc = xmax - xmin, hc = ymax - ymin;
    float c2diag = wc * wc + hc * hc;
    float ddx = x1c - x2c, ddy = y1c - y2c;
    float d2 = ddx * ddx + ddy * ddy;

    float area1 = w1 * h1, area2 = w2 * h2;
    float uni = area1 + area2 - inter;
    out[i] = 1.0f - __fdividef(inter, uni) + __fdividef(d2, c2diag);
}

extern "C" void kernel_launch(void* const* d_in, const int* in_sizes, int n_in,
                              void* d_out, int out_size)
{
    const float* pred = (const float*)d_in[0];
    const float* tgt  = (const float*)d_in[1];
    float* out = (float*)d_out;
    int n = out_size;
    int threads = 128;
    int blocks = (n + threads - 1) / threads;
    riou_kernel<<<blocks, threads>>>(pred, tgt, out, n);
}

// round 15
// speedup vs baseline: 1.0511x; 1.0511x over previous
#include <cuda_runtime.h>
#include <math.h>

// Rotated-IoU loss, one thread per pair. Reference decision structure
// (validated rel_err ~4.966e-4 across R11/R12/R13/R14). R15:
//  - R13 branchy gather (R12/R14 proved unconditional work/selects lose)
//  - edge loop exploits rectangle symmetry: E2=-E0, E3=-E1 (same for G) ->
//    4 denominators instead of 16, numerators via cross tables, all sign
//    flips folded into compile-time comparison directions
//  - cheap monotone pseudo-angle (R14, validated)
//  - warp-uniform k<=8 fast path: 8-key Batcher network (R13, validated)

__device__ __forceinline__ float pseudo_angle(float x, float y)
{
    float d = fabsf(x) + fabsf(y);
    float r = (d > 0.f) ? __fdividef(x, d) : 1.f;
    return copysignf(1.f - r, y);      // monotone w.r.t. atan2
}

__device__ __forceinline__ unsigned int order_key(float a)
{
    unsigned int u = __float_as_uint(a);
    return (u & 0x80000000u) ? ~u : (u | 0x80000000u);
}

__global__ void __launch_bounds__(128)
riou_kernel(const float* __restrict__ pred,
            const float* __restrict__ tgt,
            float* __restrict__ out, int n)
{
    int i = blockIdx.x * blockDim.x + threadIdx.x;
    if (i >= n) return;

    const float2* pp = reinterpret_cast<const float2*>(pred) + (size_t)i * 3;
    const float2* tp = reinterpret_cast<const float2*>(tgt)  + (size_t)i * 3;
    float2 a0 = pp[0], a1 = pp[1], a2 = pp[2];
    float2 b0 = tp[0], b1 = tp[1], b2 = tp[2];

    const float x1c = a0.x, y1c = a0.y, w1 = a1.x, h1 = a1.y;
    const float x2c = b0.x, y2c = b0.y, w2 = b1.x, h2 = b1.y;

    float inv1 = rsqrtf(a2.x * a2.x + a2.y * a2.y);
    float s1 = a2.x * inv1, c1 = a2.y * inv1;
    float inv2 = rsqrtf(b2.x * b2.x + b2.y * b2.y);
    float s2 = b2.x * inv2, c2 = b2.y * inv2;

    const float dxv[4] = {0.5f, -0.5f, -0.5f, 0.5f};
    const float dyv[4] = {0.5f, 0.5f, -0.5f, -0.5f};
    float c1x[4], c1y[4], c2x[4], c2y[4];
#pragma unroll
    for (int j = 0; j < 4; j++) {
        float cx = dxv[j] * w1, cy = dyv[j] * h1;
        c1x[j] = cx * c1 - cy * s1 + x1c;
        c1y[j] = cx * s1 + cy * c1 + y1c;
    }
#pragma unroll
    for (int j = 0; j < 4; j++) {
        float cx = dxv[j] * w2, cy = dyv[j] * h2;
        c2x[j] = cx * c2 - cy * s2 + x2c;
        c2y[j] = cx * s2 + cy * c2 + y2c;
    }

    // ---- gather valid candidate vertices (compacted, reference order) ----
    float2 v[16];
    int    k = 0;
    float  sumx = 0.f, sumy = 0.f;
    const float eps = 1e-6f;

    // corners of box1 inside box2
    {
        float ax = c2x[0], ay = c2y[0];
        float abx = c2x[1] - ax, aby = c2y[1] - ay;
        float adx = c2x[3] - ax, ady = c2y[3] - ay;
        float den_ab = abx * abx + aby * aby;
        float den_ad = adx * adx + ady * ady;
        float base_ab = abx * ax + aby * ay;
        float base_ad = adx * ax + ady * ay;
        float lo_ab = -eps * den_ab, hi_ab = (1.f + eps) * den_ab;
        float lo_ad = -eps * den_ad, hi_ad = (1.f + eps) * den_ad;
#pragma unroll
        for (int j = 0; j < 4; j++) {
            float d_ab = abx * c1x[j] + aby * c1y[j] - base_ab;
            float d_ad = adx * c1x[j] + ady * c1y[j] - base_ad;
            if (d_ab > lo_ab && d_ab < hi_ab && d_ad > lo_ad && d_ad < hi_ad) {
                v[k] = make_float2(c1x[j], c1y[j]);
                sumx += c1x[j]; sumy += c1y[j];
                k++;
            }
        }
    }
    // corners of box2 inside box1
    {
        float ax = c1x[0], ay = c1y[0];
        float abx = c1x[1] - ax, aby = c1y[1] - ay;
        float adx = c1x[3] - ax, ady = c1y[3] - ay;
        float den_ab = abx * abx + aby * aby;
        float den_ad = adx * adx + ady * ady;
        float base_ab = abx * ax + aby * ay;
        float base_ad = adx * ax + ady * ay;
        float lo_ab = -eps * den_ab, hi_ab = (1.f + eps) * den_ab;
        float lo_ad = -eps * den_ad, hi_ad = (1.f + eps) * den_ad;
#pragma unroll
        for (int j = 0; j < 4; j++) {
            float d_ab = abx * c2x[j] + aby * c2y[j] - base_ab;
            float d_ad = adx * c2x[j] + ady * c2y[j] - base_ad;
            if (d_ab > lo_ab && d_ab < hi_ab && d_ad > lo_ad && d_ad < hi_ad) {
                v[k] = make_float2(c2x[j], c2y[j]);
                sumx += c2x[j]; sumy += c2y[j];
                k++;
            }
        }
    }

    // ---- 4x4 edge intersections via rectangle symmetry ----
    // True edges: E2=-E0, E3=-E1, G2=-G0, G3=-G1 (exact up to corner-rounding
    // ulps). num_t(e1,e2) = sE*(A[e2]-B[e1]), num_u = sG*(C[e1]-D[e2]),
    // den = sE*sG*dr. Masks (reference: t,u strictly in (0,1)):
    //   num_t*den>0  <=> sG*ntr*dr>0 ; |num_t|<|den| <=> |ntr|<|dr|
    //   num_u*den<0  <=> sE*nur*dr<0 ; |num_u|<|dr|
    // Accept: t*E = (sE*sG)*q*Eb with q = ntr/dr.
    {
        float E0x = c1x[1] - c1x[0], E0y = c1y[1] - c1y[0];
        float E1x = c1x[2] - c1x[1], E1y = c1y[2] - c1y[1];
        float G0x = c2x[1] - c2x[0], G0y = c2y[1] - c2y[0];
        float G1x = c2x[2] - c2x[1], G1y = c2y[2] - c2y[1];

        // dr[be][bg] = Ey*Gx - Ex*Gy
        float d00 = E0y * G0x - E0x * G0y;
        float d01 = E0y * G1x - E0x * G1y;
        float d10 = E1y * G0x - E1x * G0y;
        float d11 = E1y * G1x - E1x * G1y;

        // A tables: cp(Eb, C2[j]) = Ex*c2y - Ey*c2x
        float A0[4], A1[4], D[4];
#pragma unroll
        for (int j = 0; j < 4; j++) {
            A0[j] = E0x * c2y[j] - E0y * c2x[j];
            A1[j] = E1x * c2y[j] - E1y * c2x[j];
        }
        // D[e2] = cp(Gb(e2), C2[e2])
        D[0] = G0x * c2y[0] - G0y * c2x[0];
        D[1] = G1x * c2y[1] - G1y * c2x[1];
        D[2] = G0x * c2y[2] - G0y * c2x[2];
        D[3] = G1x * c2y[3] - G1y * c2x[3];

#pragma unroll
        for (int e1 = 0; e1 < 4; e1++) {
            const int  be = e1 & 1;           // E base: 0->E0, 1->E1
            const bool sEp = (e1 < 2);        // sE = +1 ?
            float Ebx = be ? E1x : E0x, Eby = be ? E1y : E0y;
            float X1 = c1x[e1], Y1 = c1y[e1];
            float B   = Ebx * Y1 - Eby * X1;  // cp(Eb, C1[e1])
            float Cg0 = G0x * Y1 - G0y * X1;  // cp(G0, C1[e1])
            float Cg1 = G1x * Y1 - G1y * X1;  // cp(G1, C1[e1])
#pragma unroll
            for (int e2 = 0; e2 < 4; e2++) {
                const int  bg = e2 & 1;
                const bool sGp = (e2 < 2);
                float dr  = be ? (bg ? d11 : d10) : (bg ? d01 : d00);
                float ntr = (be ? A1[e2] : A0[e2]) - B;
                float nur = (bg ? Cg1 : Cg0) - D[e2];
                float adr = fabsf(dr);
                float p1 = ntr * dr;          // sG*p1 > 0 required
                float p2 = nur * dr;          // sE*p2 < 0 required
                bool ok = (sGp ? (p1 > 0.f) : (p1 < 0.f))
                        & (fabsf(ntr) < adr)
                        & (sEp ? (p2 < 0.f) : (p2 > 0.f))
                        & (fabsf(nur) < adr);
                if (ok) {
                    float q = __fdividef(ntr, dr);
                    float sq = (sEp == sGp) ? q : -q;   // (sE*sG)*q
                    float ix = X1 + sq * Ebx, iy = Y1 + sq * Eby;
                    v[k] = make_float2(ix, iy);
                    sumx += ix; sumy += iy;
                    k++;
                }
            }
        }
    }

    // ---- center ----
    float invk = __fdividef(1.f, (float)(k > 0 ? k : 1));
    float meanx = sumx * invk, meany = sumy * invk;

    float cr = 0.f;
    unsigned int mask = __activemask();
    bool small = __all_sync(mask, k <= 8);

    if (small) {
        // ===== FAST PATH: 8 register keys, Batcher n=8 network =====
        unsigned int key[8];
#pragma unroll
        for (int j = 0; j < 8; j++) {
            float2 c = v[j];
            float vx = c.x - meanx, vy = c.y - meany;
            unsigned int kj = (order_key(pseudo_angle(vx, vy)) & ~15u) | (unsigned)j;
            key[j] = (j < k) ? kj : (0xFFFFFFF0u | (unsigned)j);
        }
#define CE(a, b) { unsigned int lo = min(key[a], key[b]); \
                   unsigned int hi = max(key[a], key[b]); \
                   key[a] = lo; key[b] = hi; }
        CE(0,1) CE(2,3) CE(4,5) CE(6,7)
        CE(0,2) CE(1,3) CE(4,6) CE(5,7)
        CE(1,2) CE(5,6)
        CE(0,4) CE(1,5) CE(2,6) CE(3,7)
        CE(2,4) CE(3,5)
        CE(1,2) CE(3,4) CE(5,6)
#undef CE
        int idx0 = (int)(key[0] & 15u);
        float2 f = v[idx0];
        float fx = f.x - meanx, fy = f.y - meany;
        float prx = fx, pry = fy;
#pragma unroll
        for (int j = 1; j < 8; j++) {
            int idx = (int)(key[j] & 15u);
            idx = (j < k) ? idx : idx0;       // pad duplicates slot 0
            float2 c = v[idx];
            float cx = c.x - meanx, cy = c.y - meany;
            cr += prx * cy - pry * cx;        // at j==k this IS the wrap term
            prx = cx; pry = cy;
        }
        cr += prx * fy - pry * fx;            // zero when k<8
        cr = (k > 0) ? cr : 0.f;
    } else {
        // ===== SLOW PATH (rare): rank loop + packed-perm walk =====
        unsigned int ku[16];
#pragma unroll 4
        for (int j = 0; j < k; j++) {
            float vx = v[j].x - meanx, vy = v[j].y - meany;
            ku[j] = (order_key(pseudo_angle(vx, vy)) & ~15u) | (unsigned)j;
        }
        unsigned long long perm = 0ull;
        for (int ii = 0; ii < k; ii++) {
            unsigned int ki = ku[ii];
            int r = 0;
#pragma unroll 4
            for (int jj = 0; jj < k; jj++)
                r += (int)(ku[jj] < ki);
            perm |= (unsigned long long)(unsigned)ii << (4 * r);
        }
        if (k > 0) {
            int idx0 = (int)(perm & 15ull);
            float2 f = v[idx0];
            float fx = f.x - meanx, fy = f.y - meany;
            float prx = fx, pry = fy;
            unsigned long long pw = perm >> 4;
#pragma unroll 4
            for (int j = 1; j < k; j++) {
                int idx = (int)(pw & 15ull);
                pw >>= 4;
                float2 c = v[idx];
                float cx = c.x - meanx, cy = c.y - meany;
                cr += prx * cy - pry * cx;
                prx = cx; pry = cy;
            }
            cr += prx * fy - pry * fx;
        }
    }
    float inter = 0.5f * fabsf(cr);

    // ---- enclosing box + loss ----
    float xmin = c1x[0], xmax = c1x[0], ymin = c1y[0], ymax = c1y[0];
#pragma unroll
    for (int j = 1; j < 4; j++) {
        xmin = fminf(xmin, c1x[j]); xmax = fmaxf(xmax, c1x[j]);
        ymin = fminf(ymin, c1y[j]); ymax = fmaxf(ymax, c1y[j]);
    }
#pragma unroll
    for (int j = 0; j < 4; j++) {
        xmin = fminf(xmin, c2x[j]); xmax = fmaxf(xmax, c2x[j]);
        ymin = fminf(ymin, c2y[j]); ymax = fmaxf(ymax, c2y[j]);
    }
    float wc = xmax - xmin, hc = ymax - ymin;
    float c2diag = wc * wc + hc * hc;
    float ddx = x1c - x2c, ddy = y1c - y2c;
    float d2 = ddx * ddx + ddy * ddy;

    float area1 = w1 * h1, area2 = w2 * h2;
    float uni = area1 + area2 - inter;
    out[i] = 1.0f - __fdividef(inter, uni) + __fdividef(d2, c2diag);
}

extern "C" void kernel_launch(void* const* d_in, const int* in_sizes, int n_in,
                              void* d_out, int out_size)
{
    const float* pred = (const float*)d_in[0];
    const float* tgt  = (const float*)d_in[1];
    float* out = (float*)d_out;
    int n = out_size;
    int threads = 128;
    int blocks = (n + threads - 1) / threads;
    riou_kernel<<<blocks, threads>>>(pred, tgt, out, n);
}

// round 16
// speedup vs baseline: 1.1097x; 1.0557x over previous
#include <cuda_runtime.h>
#include <math.h>

// Rotated-IoU loss, one thread per pair. Reference decision structure
// (validated rel_err 4.4-5.0e-4 across R11-R15). R16:
//  - corner-in-box tests in the box's rotated center frame:
//    |(P-ctr).(c,s)| < w*(0.5+eps) && |(P-ctr).(-s,c)| < h*(0.5+eps)
//    (exact real-arithmetic equivalent of the reference's p_ab/p_ad bounds;
//    differs only in the validated eps-boundary ulp class)
//  - edge loop via rectangle symmetry (R15, validated)
//  - warp-uniform k<=8 fast path: 8-key Batcher network (R13, validated)
//  - cheap monotone pseudo-angle (R14, validated)

__device__ __forceinline__ float pseudo_angle(float x, float y)
{
    float d = fabsf(x) + fabsf(y);
    float r = (d > 0.f) ? __fdividef(x, d) : 1.f;
    return copysignf(1.f - r, y);      // monotone w.r.t. atan2
}

__device__ __forceinline__ unsigned int order_key(float a)
{
    unsigned int u = __float_as_uint(a);
    return (u & 0x80000000u) ? ~u : (u | 0x80000000u);
}

__global__ void __launch_bounds__(128)
riou_kernel(const float* __restrict__ pred,
            const float* __restrict__ tgt,
            float* __restrict__ out, int n)
{
    int i = blockIdx.x * blockDim.x + threadIdx.x;
    if (i >= n) return;

    const float2* pp = reinterpret_cast<const float2*>(pred) + (size_t)i * 3;
    const float2* tp = reinterpret_cast<const float2*>(tgt)  + (size_t)i * 3;
    float2 a0 = pp[0], a1 = pp[1], a2 = pp[2];
    float2 b0 = tp[0], b1 = tp[1], b2 = tp[2];

    const float x1c = a0.x, y1c = a0.y, w1 = a1.x, h1 = a1.y;
    const float x2c = b0.x, y2c = b0.y, w2 = b1.x, h2 = b1.y;

    float inv1 = rsqrtf(a2.x * a2.x + a2.y * a2.y);
    float s1 = a2.x * inv1, c1 = a2.y * inv1;
    float inv2 = rsqrtf(b2.x * b2.x + b2.y * b2.y);
    float s2 = b2.x * inv2, c2 = b2.y * inv2;

    const float dxv[4] = {0.5f, -0.5f, -0.5f, 0.5f};
    const float dyv[4] = {0.5f, 0.5f, -0.5f, -0.5f};
    float c1x[4], c1y[4], c2x[4], c2y[4];
#pragma unroll
    for (int j = 0; j < 4; j++) {
        float cx = dxv[j] * w1, cy = dyv[j] * h1;
        c1x[j] = cx * c1 - cy * s1 + x1c;
        c1y[j] = cx * s1 + cy * c1 + y1c;
    }
#pragma unroll
    for (int j = 0; j < 4; j++) {
        float cx = dxv[j] * w2, cy = dyv[j] * h2;
        c2x[j] = cx * c2 - cy * s2 + x2c;
        c2y[j] = cx * s2 + cy * c2 + y2c;
    }

    // ---- gather valid candidate vertices (compacted, reference order) ----
    float2 v[16];
    int    k = 0;
    float  sumx = 0.f, sumy = 0.f;
    const float eps = 1e-6f;

    // corners of box1 inside box2 (rotated-frame interval test)
    {
        float bw = w2 * (0.5f + eps), bh = h2 * (0.5f + eps);
#pragma unroll
        for (int j = 0; j < 4; j++) {
            float dx = c1x[j] - x2c, dy = c1y[j] - y2c;
            float u  = dx * c2 + dy * s2;
            float vv = dy * c2 - dx * s2;
            if (fabsf(u) < bw && fabsf(vv) < bh) {
                v[k] = make_float2(c1x[j], c1y[j]);
                sumx += c1x[j]; sumy += c1y[j];
                k++;
            }
        }
    }
    // corners of box2 inside box1
    {
        float bw = w1 * (0.5f + eps), bh = h1 * (0.5f + eps);
#pragma unroll
        for (int j = 0; j < 4; j++) {
            float dx = c2x[j] - x1c, dy = c2y[j] - y1c;
            float u  = dx * c1 + dy * s1;
            float vv = dy * c1 - dx * s1;
            if (fabsf(u) < bw && fabsf(vv) < bh) {
                v[k] = make_float2(c2x[j], c2y[j]);
                sumx += c2x[j]; sumy += c2y[j];
                k++;
            }
        }
    }

    // ---- 4x4 edge intersections via rectangle symmetry (R15) ----
    {
        float E0x = c1x[1] - c1x[0], E0y = c1y[1] - c1y[0];
        float E1x = c1x[2] - c1x[1], E1y = c1y[2] - c1y[1];
        float G0x = c2x[1] - c2x[0], G0y = c2y[1] - c2y[0];
        float G1x = c2x[2] - c2x[1], G1y = c2y[2] - c2y[1];

        float d00 = E0y * G0x - E0x * G0y;
        float d01 = E0y * G1x - E0x * G1y;
        float d10 = E1y * G0x - E1x * G0y;
        float d11 = E1y * G1x - E1x * G1y;

        float A0[4], A1[4], D[4];
#pragma unroll
        for (int j = 0; j < 4; j++) {
            A0[j] = E0x * c2y[j] - E0y * c2x[j];
            A1[j] = E1x * c2y[j] - E1y * c2x[j];
        }
        D[0] = G0x * c2y[0] - G0y * c2x[0];
        D[1] = G1x * c2y[1] - G1y * c2x[1];
        D[2] = G0x * c2y[2] - G0y * c2x[2];
        D[3] = G1x * c2y[3] - G1y * c2x[3];

#pragma unroll
        for (int e1 = 0; e1 < 4; e1++) {
            const int  be = e1 & 1;
            const bool sEp = (e1 < 2);
            float Ebx = be ? E1x : E0x, Eby = be ? E1y : E0y;
            float X1 = c1x[e1], Y1 = c1y[e1];
            float B   = Ebx * Y1 - Eby * X1;
            float Cg0 = G0x * Y1 - G0y * X1;
            float Cg1 = G1x * Y1 - G1y * X1;
#pragma unroll
            for (int e2 = 0; e2 < 4; e2++) {
                const int  bg = e2 & 1;
                const bool sGp = (e2 < 2);
                float dr  = be ? (bg ? d11 : d10) : (bg ? d01 : d00);
                float ntr = (be ? A1[e2] : A0[e2]) - B;
                float nur = (bg ? Cg1 : Cg0) - D[e2];
                float adr = fabsf(dr);
                float p1 = ntr * dr;
                float p2 = nur * dr;
                bool ok = (sGp ? (p1 > 0.f) : (p1 < 0.f))
                        & (fabsf(ntr) < adr)
                        & (sEp ? (p2 < 0.f) : (p2 > 0.f))
                        & (fabsf(nur) < adr);
                if (ok) {
                    float q = __fdividef(ntr, dr);
                    float sq = (sEp == sGp) ? q : -q;
                    float ix = X1 + sq * Ebx, iy = Y1 + sq * Eby;
                    v[k] = make_float2(ix, iy);
                    sumx += ix; sumy += iy;
                    k++;
                }
            }
        }
    }

    // ---- center ----
    float invk = __fdividef(1.f, (float)(k > 0 ? k : 1));
    float meanx = sumx * invk, meany = sumy * invk;

    float cr = 0.f;
    unsigned int mask = __activemask();
    bool small = __all_sync(mask, k <= 8);

    if (small) {
        // ===== FAST PATH: 8 register keys, Batcher n=8 network =====
        unsigned int key[8];
#pragma unroll
        for (int j = 0; j < 8; j++) {
            float2 c = v[j];
            float vx = c.x - meanx, vy = c.y - meany;
            unsigned int kj = (order_key(pseudo_angle(vx, vy)) & ~15u) | (unsigned)j;
            key[j] = (j < k) ? kj : (0xFFFFFFF0u | (unsigned)j);
        }
#define CE(a, b) { unsigned int lo = min(key[a], key[b]); \
                   unsigned int hi = max(key[a], key[b]); \
                   key[a] = lo; key[b] = hi; }
        CE(0,1) CE(2,3) CE(4,5) CE(6,7)
        CE(0,2) CE(1,3) CE(4,6) CE(5,7)
        CE(1,2) CE(5,6)
        CE(0,4) CE(1,5) CE(2,6) CE(3,7)
        CE(2,4) CE(3,5)
        CE(1,2) CE(3,4) CE(5,6)
#undef CE
        int idx0 = (int)(key[0] & 15u);
        float2 f = v[idx0];
        float fx = f.x - meanx, fy = f.y - meany;
        float prx = fx, pry = fy;
#pragma unroll
        for (int j = 1; j < 8; j++) {
            int idx = (int)(key[j] & 15u);
            idx = (j < k) ? idx : idx0;       // pad duplicates slot 0
            float2 c = v[idx];
            float cx = c.x - meanx, cy = c.y - meany;
            cr += prx * cy - pry * cx;        // at j==k this IS the wrap term
            prx = cx; pry = cy;
        }
        cr += prx * fy - pry * fx;            // zero when k<8
        cr = (k > 0) ? cr : 0.f;
    } else {
        // ===== SLOW PATH (rare): rank loop + packed-perm walk =====
        unsigned int ku[16];
#pragma unroll 4
        for (int j = 0; j < k; j++) {
            float vx = v[j].x - meanx, vy = v[j].y - meany;
            ku[j] = (order_key(pseudo_angle(vx, vy)) & ~15u) | (unsigned)j;
        }
        unsigned long long perm = 0ull;
        for (int ii = 0; ii < k; ii++) {
            unsigned int ki = ku[ii];
            int r = 0;
#pragma unroll 4
            for (int jj = 0; jj < k; jj++)
                r += (int)(ku[jj] < ki);
            perm |= (unsigned long long)(unsigned)ii << (4 * r);
        }
        if (k > 0) {
            int idx0 = (int)(perm & 15ull);
            float2 f = v[idx0];
            float fx = f.x - meanx, fy = f.y - meany;
            float prx = fx, pry = fy;
            unsigned long long pw = perm >> 4;
#pragma unroll 4
            for (int j = 1; j < k; j++) {
                int idx = (int)(pw & 15ull);
                pw >>= 4;
                float2 c = v[idx];
                float cx = c.x - meanx, cy = c.y - meany;
                cr += prx * cy - pry * cx;
                prx = cx; pry = cy;
            }
            cr += prx * fy - pry * fx;
        }
    }
    float inter = 0.5f * fabsf(cr);

    // ---- enclosing box + loss ----
    float xmin = c1x[0], xmax = c1x[0], ymin = c1y[0], ymax = c1y[0];
#pragma unroll
    for (int j = 1; j < 4; j++) {
        xmin = fminf(xmin, c1x[j]); xmax = fmaxf(xmax, c1x[j]);
        ymin = fminf(ymin, c1y[j]); ymax = fmaxf(ymax, c1y[j]);
    }
#pragma unroll
    for (int j = 0; j < 4; j++) {
        xmin = fminf(xmin, c2x[j]); xmax = fmaxf(xmax, c2x[j]);
        ymin = fminf(ymin, c2y[j]); ymax = fmaxf(ymax, c2y[j]);
    }
    float wc = xmax - xmin, hc = ymax - ymin;
    float c2diag = wc * wc + hc * hc;
    float ddx = x1c - x2c, ddy = y1c - y2c;
    float d2 = ddx * ddx + ddy * ddy;

    float area1 = w1 * h1, area2 = w2 * h2;
    float uni = area1 + area2 - inter;
    out[i] = 1.0f - __fdividef(inter, uni) + __fdividef(d2, c2diag);
}

extern "C" void kernel_launch(void* const* d_in, const int* in_sizes, int n_in,
                              void* d_out, int out_size)
{
    const float* pred = (const float*)d_in[0];
    const float* tgt  = (const float*)d_in[1];
    float* out = (float*)d_out;
    int n = out_size;
    int threads = 128;
    int blocks = (n + threads - 1) / threads;
    riou_kernel<<<blocks, threads>>>(pred, tgt, out, n);
}